// round 1
// baseline (speedup 1.0000x reference)
#include <cuda_runtime.h>
#include <cuda_bf16.h>
#include <math.h>

// Problem constants
#define LAYERS 2
#define DMODEL 2048
#define NHEAD  16
#define HDIM   128
#define FFDIM  5632
#define RLORA  16
#define BATCH  4
#define SEQ    512
#define BB     8            // combined batch (text + mis)
#define MTOK   (BB*SEQ)     // 4096 tokens
#define LORA_SCALE 1.4f

// ---------------- scratch (static device globals; allocation-free) ----------------
__device__ float g_h   [MTOK * DMODEL];
__device__ float g_x   [MTOK * DMODEL];
__device__ float g_q   [MTOK * DMODEL];
__device__ float g_k   [MTOK * DMODEL];
__device__ float g_v   [MTOK * DMODEL];
__device__ float g_o   [MTOK * DMODEL];
__device__ float g_sc  [BB * NHEAD * SEQ * SEQ];
__device__ float g_gate[MTOK * FFDIM];
__device__ float g_up  [MTOK * FFDIM];
__device__ float g_t   [MTOK * RLORA];
__device__ float g_reps[BB * DMODEL];

// ---------------- embedding gather ----------------
__global__ void embed_kernel(const int* __restrict__ idT, const int* __restrict__ idM,
                             const float* __restrict__ E, float* __restrict__ H)
{
    int t  = blockIdx.x;           // token 0..4095
    int bb = t >> 9;
    int s  = t & 511;
    int id = (bb < 4) ? idT[bb * SEQ + s] : idM[(bb - 4) * SEQ + s];
    const float4* src = reinterpret_cast<const float4*>(E + (size_t)id * DMODEL);
    float4*       dst = reinterpret_cast<float4*>(H + (size_t)t * DMODEL);
    for (int j = threadIdx.x; j < DMODEL / 4; j += blockDim.x) dst[j] = src[j];
}

// ---------------- rmsnorm (row per block) ----------------
__global__ void rmsnorm_kernel(const float* __restrict__ H, const float* __restrict__ W,
                               float* __restrict__ X)
{
    __shared__ float red[256];
    int row = blockIdx.x;
    const float* h = H + (size_t)row * DMODEL;
    float s = 0.f;
    for (int j = threadIdx.x; j < DMODEL; j += 256) { float v = h[j]; s += v * v; }
    red[threadIdx.x] = s; __syncthreads();
    for (int o = 128; o > 0; o >>= 1) {
        if (threadIdx.x < o) red[threadIdx.x] += red[threadIdx.x + o];
        __syncthreads();
    }
    float scale = rsqrtf(red[0] / (float)DMODEL + 1e-6f);
    float* x = X + (size_t)row * DMODEL;
    for (int j = threadIdx.x; j < DMODEL; j += 256) x[j] = h[j] * scale * W[j];
}

// ---------------- lora down-projection: T = X @ A   (M x K x 16) ----------------
__global__ void lora_t_kernel(const float* __restrict__ X, const float* __restrict__ A,
                              float* __restrict__ T, int K)
{
    int row = blockIdx.x * 16 + (threadIdx.x >> 4);
    int r   = threadIdx.x & 15;
    const float* x = X + (size_t)row * K;
    float acc = 0.f;
    #pragma unroll 4
    for (int k = 0; k < K; k++) acc += x[k] * A[k * RLORA + r];
    T[row * RLORA + r] = acc;
}

// ---------------- main SGEMM: C = A@W (+ 1.4 * T@LB) (+= if accum) ----------------
// 128x128 tile, BK=16, 256 threads, 8x8 per thread
__global__ __launch_bounds__(256)
void gemm_kernel(const float* __restrict__ A, const float* __restrict__ W,
                 float* __restrict__ C, int M, int N, int K,
                 const float* __restrict__ lT, const float* __restrict__ lB,
                 int accum)
{
    __shared__ float As[16][128];
    __shared__ float Bs[16][128];
    __shared__ float Ls[16][128];

    const int tid = threadIdx.x;
    const int tx  = tid & 15;     // n
    const int ty  = tid >> 4;     // m
    const int bm  = blockIdx.y * 128;
    const int bn  = blockIdx.x * 128;

    if (lT) {
        for (int f = tid; f < 512; f += 256) {
            int r = f >> 5;
            int c = (f & 31) << 2;
            float4 v = *reinterpret_cast<const float4*>(&lB[(size_t)r * N + bn + c]);
            *reinterpret_cast<float4*>(&Ls[r][c]) = v;
        }
    }

    float acc[8][8];
    #pragma unroll
    for (int i = 0; i < 8; i++)
        #pragma unroll
        for (int j = 0; j < 8; j++) acc[i][j] = 0.f;

    for (int k0 = 0; k0 < K; k0 += 16) {
        for (int f = tid; f < 512; f += 256) {            // A: 128x16 (transpose into smem)
            int r = f >> 2;
            int c = (f & 3) << 2;
            float4 v = *reinterpret_cast<const float4*>(&A[(size_t)(bm + r) * K + k0 + c]);
            As[c + 0][r] = v.x; As[c + 1][r] = v.y; As[c + 2][r] = v.z; As[c + 3][r] = v.w;
        }
        for (int f = tid; f < 512; f += 256) {            // W: 16x128
            int r = f >> 5;
            int c = (f & 31) << 2;
            float4 v = *reinterpret_cast<const float4*>(&W[(size_t)(k0 + r) * N + bn + c]);
            *reinterpret_cast<float4*>(&Bs[r][c]) = v;
        }
        __syncthreads();
        #pragma unroll
        for (int k = 0; k < 16; k++) {
            float4 a0 = *reinterpret_cast<const float4*>(&As[k][ty * 8]);
            float4 a1 = *reinterpret_cast<const float4*>(&As[k][ty * 8 + 4]);
            float4 b0 = *reinterpret_cast<const float4*>(&Bs[k][tx * 8]);
            float4 b1 = *reinterpret_cast<const float4*>(&Bs[k][tx * 8 + 4]);
            float ra[8] = {a0.x, a0.y, a0.z, a0.w, a1.x, a1.y, a1.z, a1.w};
            float rb[8] = {b0.x, b0.y, b0.z, b0.w, b1.x, b1.y, b1.z, b1.w};
            #pragma unroll
            for (int i = 0; i < 8; i++)
                #pragma unroll
                for (int j = 0; j < 8; j++) acc[i][j] += ra[i] * rb[j];
        }
        __syncthreads();
    }

    #pragma unroll
    for (int i = 0; i < 8; i++) {
        int row = bm + ty * 8 + i;
        if (lT) {
            float4 t0 = *reinterpret_cast<const float4*>(&lT[row * RLORA + 0]);
            float4 t1 = *reinterpret_cast<const float4*>(&lT[row * RLORA + 4]);
            float4 t2 = *reinterpret_cast<const float4*>(&lT[row * RLORA + 8]);
            float4 t3 = *reinterpret_cast<const float4*>(&lT[row * RLORA + 12]);
            float tv[16] = {t0.x, t0.y, t0.z, t0.w, t1.x, t1.y, t1.z, t1.w,
                            t2.x, t2.y, t2.z, t2.w, t3.x, t3.y, t3.z, t3.w};
            #pragma unroll
            for (int r = 0; r < 16; r++) {
                float tvr = LORA_SCALE * tv[r];
                #pragma unroll
                for (int j = 0; j < 8; j++) acc[i][j] += tvr * Ls[r][tx * 8 + j];
            }
        }
        float* Crow = &C[(size_t)row * N + bn + tx * 8];
        float4 c0 = make_float4(acc[i][0], acc[i][1], acc[i][2], acc[i][3]);
        float4 c1 = make_float4(acc[i][4], acc[i][5], acc[i][6], acc[i][7]);
        if (accum) {
            float4 o0 = *reinterpret_cast<const float4*>(Crow);
            float4 o1 = *reinterpret_cast<const float4*>(Crow + 4);
            c0.x += o0.x; c0.y += o0.y; c0.z += o0.z; c0.w += o0.w;
            c1.x += o1.x; c1.y += o1.y; c1.z += o1.z; c1.w += o1.w;
        }
        *reinterpret_cast<float4*>(Crow)     = c0;
        *reinterpret_cast<float4*>(Crow + 4) = c1;
    }
}

// ---------------- RoPE on q and k ----------------
__global__ void rope_kernel(float* __restrict__ Q, float* __restrict__ Kt)
{
    int i = blockIdx.x * blockDim.x + threadIdx.x;   // MTOK * NHEAD * 64
    if (i >= MTOK * NHEAD * 64) return;
    int d = i & 63;
    int h = (i >> 6) & 15;
    int t = i >> 10;
    int s = t & 511;
    float freq = expf(-(float)d * (logf(10000.f) / 64.f));
    float ang = (float)s * freq;
    float sn, cs;
    sincosf(ang, &sn, &cs);
    size_t base = (size_t)t * DMODEL + h * HDIM + d;
    float x1 = Q[base], x2 = Q[base + 64];
    Q[base]      = x1 * cs - x2 * sn;
    Q[base + 64] = x1 * sn + x2 * cs;
    x1 = Kt[base]; x2 = Kt[base + 64];
    Kt[base]      = x1 * cs - x2 * sn;
    Kt[base + 64] = x1 * sn + x2 * cs;
}

// ---------------- attention scores + mask bias ----------------
__global__ void scores_kernel(const float* __restrict__ Q, const float* __restrict__ Kt,
                              const int* __restrict__ mT, const int* __restrict__ mM,
                              float* __restrict__ S_)
{
    __shared__ float qs[16][132];
    __shared__ float ks[16][132];
    int z  = blockIdx.z;             // bb*16 + h
    int bb = z >> 4;
    int h  = z & 15;
    int q0 = blockIdx.y * 16;
    int k0 = blockIdx.x * 16;
    int tid = threadIdx.y * 16 + threadIdx.x;
    for (int f = tid; f < 512; f += 256) {
        int r = f >> 5;
        int c = (f & 31) << 2;
        float4 vq = *reinterpret_cast<const float4*>(
            &Q[(size_t)(bb * SEQ + q0 + r) * DMODEL + h * HDIM + c]);
        qs[r][c] = vq.x; qs[r][c + 1] = vq.y; qs[r][c + 2] = vq.z; qs[r][c + 3] = vq.w;
        float4 vk = *reinterpret_cast<const float4*>(
            &Kt[(size_t)(bb * SEQ + k0 + r) * DMODEL + h * HDIM + c]);
        ks[r][c] = vk.x; ks[r][c + 1] = vk.y; ks[r][c + 2] = vk.z; ks[r][c + 3] = vk.w;
    }
    __syncthreads();
    int qi = threadIdx.y, kj = threadIdx.x;
    float acc = 0.f;
    #pragma unroll 8
    for (int d = 0; d < HDIM; d++) acc += qs[qi][d] * ks[kj][d];
    int sq = q0 + qi, sk = k0 + kj;
    const int* mask = (bb < 4) ? (mT + bb * SEQ) : (mM + (bb - 4) * SEQ);
    bool ok = (sk <= sq) && (mask[sk] > 0);
    float val = acc * 0.08838834764831845f + (ok ? 0.f : -1e9f);
    S_[((size_t)z * SEQ + sq) * SEQ + sk] = val;
}

// ---------------- row softmax (512 per row) ----------------
__global__ void softmax_kernel(float* __restrict__ S_)
{
    __shared__ float red[256];
    float* p = S_ + (size_t)blockIdx.x * SEQ;
    int t = threadIdx.x;
    float v0 = p[t], v1 = p[t + 256];
    float m = fmaxf(v0, v1);
    red[t] = m; __syncthreads();
    for (int o = 128; o > 0; o >>= 1) {
        if (t < o) red[t] = fmaxf(red[t], red[t + o]);
        __syncthreads();
    }
    m = red[0]; __syncthreads();
    float e0 = expf(v0 - m), e1 = expf(v1 - m);
    red[t] = e0 + e1; __syncthreads();
    for (int o = 128; o > 0; o >>= 1) {
        if (t < o) red[t] += red[t + o];
        __syncthreads();
    }
    float inv = 1.f / red[0];
    p[t] = e0 * inv; p[t + 256] = e1 * inv;
}

// ---------------- O = attn @ V ----------------
__global__ void attnv_kernel(const float* __restrict__ P, const float* __restrict__ V,
                             float* __restrict__ O)
{
    __shared__ float vs[16][128];
    __shared__ float as[4][16];
    int z  = blockIdx.y;
    int bb = z >> 4;
    int h  = z & 15;
    int q0 = blockIdx.x * 4;
    int tx = threadIdx.x;    // 0..127 (head dim)
    int ty = threadIdx.y;    // 0..3  (q row)
    int tid = ty * 128 + tx;
    const float* Prow = P + ((size_t)z * SEQ + q0) * SEQ;
    float acc = 0.f;
    for (int kt = 0; kt < SEQ; kt += 16) {
        for (int f = tid; f < 2048; f += 512) {
            int r = f >> 7, c = f & 127;
            vs[r][c] = V[(size_t)(bb * SEQ + kt + r) * DMODEL + h * HDIM + c];
        }
        if (tid < 64) {
            int r = tid >> 4, c = tid & 15;
            as[r][c] = Prow[r * SEQ + kt + c];
        }
        __syncthreads();
        #pragma unroll
        for (int kk = 0; kk < 16; kk++) acc += as[ty][kk] * vs[kk][tx];
        __syncthreads();
    }
    O[(size_t)(bb * SEQ + q0 + ty) * DMODEL + h * HDIM + tx] = acc;
}

// ---------------- swiglu: G = silu(G) * U ----------------
__global__ void swiglu_kernel(float* __restrict__ G, const float* __restrict__ U)
{
    size_t i = (size_t)blockIdx.x * blockDim.x + threadIdx.x;
    if (i >= (size_t)MTOK * FFDIM) return;
    float g = G[i];
    float sig = 1.f / (1.f + expf(-g));
    G[i] = g * sig * U[i];
}

// ---------------- reps extraction + L2 normalize ----------------
__global__ void reps_kernel(const float* __restrict__ X, const int* __restrict__ mT,
                            const int* __restrict__ mM, float* __restrict__ R_)
{
    __shared__ int ired[256];
    __shared__ float fred[256];
    __shared__ int sidx;
    int bb = blockIdx.x;
    const int* mask = (bb < 4) ? mT : mM;
    int b = bb & 3;
    int t = threadIdx.x;
    int s = 0;
    for (int j = t; j < SEQ; j += 256) s += mask[b * SEQ + j];
    ired[t] = s; __syncthreads();
    for (int o = 128; o > 0; o >>= 1) {
        if (t < o) ired[t] += ired[t + o];
        __syncthreads();
    }
    if (t == 0) {
        int last = mask[0 * SEQ + 511] + mask[1 * SEQ + 511] +
                   mask[2 * SEQ + 511] + mask[3 * SEQ + 511];
        sidx = (last == BATCH) ? (SEQ - 1) : (ired[0] - 1);
    }
    __syncthreads();
    const float* row = X + (size_t)(bb * SEQ + sidx) * DMODEL;
    float ss = 0.f;
    for (int j = t; j < DMODEL; j += 256) { float v = row[j]; ss += v * v; }
    fred[t] = ss; __syncthreads();
    for (int o = 128; o > 0; o >>= 1) {
        if (t < o) fred[t] += fred[t + o];
        __syncthreads();
    }
    float inv = 1.f / sqrtf(fred[0]);
    for (int j = t; j < DMODEL; j += 256) R_[bb * DMODEL + j] = row[j] * inv;
}

// ---------------- contrastive loss ----------------
__global__ void loss_kernel(const float* __restrict__ R_, float* __restrict__ out)
{
    __shared__ float sims[16];
    int tid = threadIdx.x;
    int warp = tid >> 5, lane = tid & 31;
    for (int p = warp; p < 16; p += 8) {
        int i = p >> 2, j = p & 3;
        const float* a = R_ + i * DMODEL;
        const float* bR = R_ + (4 + j) * DMODEL;
        float d = 0.f;
        for (int k2 = lane; k2 < DMODEL; k2 += 32) d += a[k2] * bR[k2];
        #pragma unroll
        for (int o = 16; o > 0; o >>= 1) d += __shfl_xor_sync(0xffffffff, d, o);
        if (lane == 0) sims[p] = d * 20.f;     // / TEMP(0.05)
    }
    __syncthreads();
    if (tid == 0) {
        float loss = 0.f;
        for (int i = 0; i < 4; i++) {
            float m = -1e30f;
            for (int j = 0; j < 4; j++) m = fmaxf(m, sims[i * 4 + j]);
            float sum = 0.f;
            for (int j = 0; j < 4; j++) sum += expf(sims[i * 4 + j] - m);
            loss += (logf(sum) + m) - sims[i * 4 + i];
        }
        out[0] = loss * 0.25f;
    }
}

// ---------------- host driver ----------------
static float* symaddr(const void* sym)
{
    void* p = nullptr;
    cudaGetSymbolAddress(&p, sym);
    return (float*)p;
}

extern "C" void kernel_launch(void* const* d_in, const int* in_sizes, int n_in,
                              void* d_out, int out_size)
{
    const int*   idT = (const int*)d_in[0];
    const int*   mT  = (const int*)d_in[1];
    const int*   idM = (const int*)d_in[2];
    const int*   mM  = (const int*)d_in[3];
    const float* emb = (const float*)d_in[4];
    const float* ln1 = (const float*)d_in[5];
    const float* ln2 = (const float*)d_in[6];
    const float* lnf = (const float*)d_in[7];
    const float* Wq = (const float*)d_in[8],  *Aq = (const float*)d_in[9],  *Bq = (const float*)d_in[10];
    const float* Wk = (const float*)d_in[11], *Ak = (const float*)d_in[12], *Bk = (const float*)d_in[13];
    const float* Wv = (const float*)d_in[14], *Av = (const float*)d_in[15], *Bv = (const float*)d_in[16];
    const float* Wo = (const float*)d_in[17], *Ao = (const float*)d_in[18], *Bo = (const float*)d_in[19];
    const float* Wg = (const float*)d_in[20], *Ag = (const float*)d_in[21], *Bg = (const float*)d_in[22];
    const float* Wu = (const float*)d_in[23], *Au = (const float*)d_in[24], *Bu = (const float*)d_in[25];
    const float* Wd = (const float*)d_in[26], *Ad = (const float*)d_in[27], *Bd = (const float*)d_in[28];

    float* h  = symaddr(g_h);
    float* x  = symaddr(g_x);
    float* q  = symaddr(g_q);
    float* k  = symaddr(g_k);
    float* v  = symaddr(g_v);
    float* o  = symaddr(g_o);
    float* sc = symaddr(g_sc);
    float* gg = symaddr(g_gate);
    float* uu = symaddr(g_up);
    float* t  = symaddr(g_t);
    float* rp = symaddr(g_reps);

    embed_kernel<<<MTOK, 256>>>(idT, idM, emb, h);

    const dim3 gD(DMODEL / 128, MTOK / 128);   // N=2048
    const dim3 gF(FFDIM / 128, MTOK / 128);    // N=5632

    for (int l = 0; l < LAYERS; l++) {
        const float* Wq_l = Wq + (size_t)l * DMODEL * DMODEL;
        const float* Wk_l = Wk + (size_t)l * DMODEL * DMODEL;
        const float* Wv_l = Wv + (size_t)l * DMODEL * DMODEL;
        const float* Wo_l = Wo + (size_t)l * DMODEL * DMODEL;
        const float* Wg_l = Wg + (size_t)l * DMODEL * FFDIM;
        const float* Wu_l = Wu + (size_t)l * DMODEL * FFDIM;
        const float* Wd_l = Wd + (size_t)l * FFDIM * DMODEL;
        const float* Aq_l = Aq + (size_t)l * DMODEL * RLORA;
        const float* Ak_l = Ak + (size_t)l * DMODEL * RLORA;
        const float* Av_l = Av + (size_t)l * DMODEL * RLORA;
        const float* Ao_l = Ao + (size_t)l * DMODEL * RLORA;
        const float* Ag_l = Ag + (size_t)l * DMODEL * RLORA;
        const float* Au_l = Au + (size_t)l * DMODEL * RLORA;
        const float* Ad_l = Ad + (size_t)l * FFDIM * RLORA;
        const float* Bq_l = Bq + (size_t)l * RLORA * DMODEL;
        const float* Bk_l = Bk + (size_t)l * RLORA * DMODEL;
        const float* Bv_l = Bv + (size_t)l * RLORA * DMODEL;
        const float* Bo_l = Bo + (size_t)l * RLORA * DMODEL;
        const float* Bg_l = Bg + (size_t)l * RLORA * FFDIM;
        const float* Bu_l = Bu + (size_t)l * RLORA * FFDIM;
        const float* Bd_l = Bd + (size_t)l * RLORA * DMODEL;

        rmsnorm_kernel<<<MTOK, 256>>>(h, ln1 + l * DMODEL, x);

        lora_t_kernel<<<MTOK / 16, 256>>>(x, Aq_l, t, DMODEL);
        gemm_kernel<<<gD, 256>>>(x, Wq_l, q, MTOK, DMODEL, DMODEL, t, Bq_l, 0);
        lora_t_kernel<<<MTOK / 16, 256>>>(x, Ak_l, t, DMODEL);
        gemm_kernel<<<gD, 256>>>(x, Wk_l, k, MTOK, DMODEL, DMODEL, t, Bk_l, 0);
        lora_t_kernel<<<MTOK / 16, 256>>>(x, Av_l, t, DMODEL);
        gemm_kernel<<<gD, 256>>>(x, Wv_l, v, MTOK, DMODEL, DMODEL, t, Bv_l, 0);

        rope_kernel<<<(MTOK * NHEAD * 64 + 255) / 256, 256>>>(q, k);

        scores_kernel<<<dim3(SEQ / 16, SEQ / 16, BB * NHEAD), dim3(16, 16)>>>(q, k, mT, mM, sc);
        softmax_kernel<<<BB * NHEAD * SEQ, 256>>>(sc);
        attnv_kernel<<<dim3(SEQ / 4, BB * NHEAD), dim3(128, 4)>>>(sc, v, o);

        lora_t_kernel<<<MTOK / 16, 256>>>(o, Ao_l, t, DMODEL);
        gemm_kernel<<<gD, 256>>>(o, Wo_l, h, MTOK, DMODEL, DMODEL, t, Bo_l, 1);

        rmsnorm_kernel<<<MTOK, 256>>>(h, ln2 + l * DMODEL, x);

        lora_t_kernel<<<MTOK / 16, 256>>>(x, Ag_l, t, DMODEL);
        gemm_kernel<<<gF, 256>>>(x, Wg_l, gg, MTOK, FFDIM, DMODEL, t, Bg_l, 0);
        lora_t_kernel<<<MTOK / 16, 256>>>(x, Au_l, t, DMODEL);
        gemm_kernel<<<gF, 256>>>(x, Wu_l, uu, MTOK, FFDIM, DMODEL, t, Bu_l, 0);

        swiglu_kernel<<<(int)(((size_t)MTOK * FFDIM + 255) / 256), 256>>>(gg, uu);

        lora_t_kernel<<<MTOK / 16, 256>>>(gg, Ad_l, t, FFDIM);
        gemm_kernel<<<gD, 256>>>(gg, Wd_l, h, MTOK, DMODEL, FFDIM, t, Bd_l, 1);
    }

    rmsnorm_kernel<<<MTOK, 256>>>(h, lnf, x);
    reps_kernel<<<BB, 256>>>(x, mT, mM, rp);
    loss_kernel<<<1, 256>>>(rp, (float*)d_out);
}